// round 6
// baseline (speedup 1.0000x reference)
#include <cuda_runtime.h>
#include <math.h>
#include <stdint.h>

#define SEQ    4096
#define NH     16
#define HD     80
#define HIDDEN 1280
#define QKVN   3840
#define INV_SCALE 0.11180339887498948f   // 1/sqrt(80)

// -------- scratch (no allocation allowed -> __device__ globals) --------
__device__ float g_qkv [SEQ * QKVN];    // 62.9 MB : [seq][3*hidden]
__device__ float g_attn[SEQ * HIDDEN];  // 21.0 MB : attention output

// =====================================================================
// SGEMM: C[M,N] = A[M,K] @ B[K,N] + bias[N]   (fp32, 128x128x8)
// =====================================================================
__global__ void __launch_bounds__(256)
sgemm_bias(const float* __restrict__ A, const float* __restrict__ B,
           const float* __restrict__ bias, float* __restrict__ C,
           int M, int N, int K)
{
    const int BM = 128, BN = 128, BK = 8, TM = 8, TN = 8;
    __shared__ float As[BK][BM];
    __shared__ float Bs[BK][BN];

    int tid = threadIdx.x;
    int tx = tid % 16;
    int ty = tid / 16;
    int bx = blockIdx.x, by = blockIdx.y;

    const float* Ab = A + (size_t)by * BM * K;
    const float* Bb = B + (size_t)bx * BN;

    int arow = tid >> 1;
    int acol = (tid & 1) * 4;
    int brow = tid >> 5;
    int bcol = (tid & 31) * 4;

    float acc[TM][TN];
    #pragma unroll
    for (int i = 0; i < TM; i++)
        #pragma unroll
        for (int j = 0; j < TN; j++) acc[i][j] = 0.f;

    for (int k0 = 0; k0 < K; k0 += BK) {
        float4 a4 = *(const float4*)&Ab[(size_t)arow * K + k0 + acol];
        As[acol + 0][arow] = a4.x;
        As[acol + 1][arow] = a4.y;
        As[acol + 2][arow] = a4.z;
        As[acol + 3][arow] = a4.w;
        float4 b4 = *(const float4*)&Bb[(size_t)(k0 + brow) * N + bcol];
        *(float4*)&Bs[brow][bcol] = b4;
        __syncthreads();

        #pragma unroll
        for (int k = 0; k < BK; k++) {
            float ra[TM], rb[TN];
            *(float4*)&ra[0] = *(const float4*)&As[k][ty * TM];
            *(float4*)&ra[4] = *(const float4*)&As[k][ty * TM + 4];
            *(float4*)&rb[0] = *(const float4*)&Bs[k][tx * TN];
            *(float4*)&rb[4] = *(const float4*)&Bs[k][tx * TN + 4];
            #pragma unroll
            for (int i = 0; i < TM; i++)
                #pragma unroll
                for (int j = 0; j < TN; j++)
                    acc[i][j] = fmaf(ra[i], rb[j], acc[i][j]);
        }
        __syncthreads();
    }

    #pragma unroll
    for (int i = 0; i < TM; i++) {
        size_t row = (size_t)by * BM + ty * TM + i;
        #pragma unroll
        for (int j = 0; j < TN; j += 4) {
            int col = bx * BN + tx * TN + j;
            float4 c4;
            c4.x = acc[i][j + 0] + bias[col + 0];
            c4.y = acc[i][j + 1] + bias[col + 1];
            c4.z = acc[i][j + 2] + bias[col + 2];
            c4.w = acc[i][j + 3] + bias[col + 3];
            *(float4*)&C[row * N + col] = c4;
        }
    }
}

// =====================================================================
// RoPE in-place on Q and K halves of g_qkv.
// =====================================================================
__global__ void rope_kernel(const float* __restrict__ cosE,
                            const float* __restrict__ sinE)
{
    int idx = blockIdx.x * blockDim.x + threadIdx.x;
    const int TOT = 2 * SEQ * NH * (HD / 2);
    if (idx >= TOT) return;
    int d    = idx % 40;
    int h    = (idx / 40) % NH;
    int s    = (idx / (40 * NH)) % SEQ;
    int part = idx / (40 * NH * SEQ);

    float* p = g_qkv + (size_t)s * QKVN + part * HIDDEN + h * HD;
    float t1 = p[d], t2 = p[d + 40];
    float c1 = cosE[s * HD + d],      s1 = sinE[s * HD + d];
    float c2 = cosE[s * HD + d + 40], s2 = sinE[s * HD + d + 40];
    p[d]      = t1 * c1 - t2 * s1;
    p[d + 40] = t2 * c2 + t1 * s2;
}

// =====================================================================
// TF32 tensor-core flash attention.
// grid=(SEQ/128, NH), 256 threads = 8 warps; each warp owns 16 query rows.
// mma.sync.m16n8k8 tf32. Q fragments register-resident across KV loop.
// Smem: Ks[128][84], Vs[128][88], Ss[128][132] (pads = conflict-free frags).
// =====================================================================
#define PK 84
#define PVp 88
#define PS 132
#define FA_SMEM_BYTES ((128*PK + 128*PVp + 128*PS) * 4)

__device__ __forceinline__ float cvt_tf32(float x) {
    uint32_t u;
    asm("cvt.rna.tf32.f32 %0, %1;" : "=r"(u) : "f"(x));
    return __uint_as_float(u);
}

__device__ __forceinline__ void mma_tf32(float* c,
    uint32_t a0, uint32_t a1, uint32_t a2, uint32_t a3,
    uint32_t b0, uint32_t b1)
{
    asm volatile(
        "mma.sync.aligned.m16n8k8.row.col.f32.tf32.tf32.f32 "
        "{%0,%1,%2,%3}, {%4,%5,%6,%7}, {%8,%9}, {%0,%1,%2,%3};\n"
        : "+f"(c[0]), "+f"(c[1]), "+f"(c[2]), "+f"(c[3])
        : "r"(a0), "r"(a1), "r"(a2), "r"(a3), "r"(b0), "r"(b1));
}

__global__ void __launch_bounds__(256, 1)
flash_attn_tc()
{
    extern __shared__ float sm[];
    float* Ks = sm;                    // [128][PK]
    float* Vs = Ks + 128 * PK;         // [128][PVp]
    float* Ss = Vs + 128 * PVp;        // [128][PS]; also Q staging (pad PK)

    int tid  = threadIdx.x;
    int lane = tid & 31;
    int w    = tid >> 5;               // warp 0..7 -> rows 16w..16w+15
    int g    = lane >> 2;              // group id (row within octet)
    int t    = lane & 3;               // thread in group
    int h    = blockIdx.y;
    int q0   = blockIdx.x * 128;

    // ---- stage Q (scaled + tf32-rounded) into Ss with pad PK ----
    const float* qg = g_qkv + (size_t)q0 * QKVN + h * HD;
    for (int i = tid; i < 128 * 20; i += 256) {
        int r = i / 20, c = i % 20;
        float4 v = *(const float4*)&qg[(size_t)r * QKVN + 4 * c];
        v.x = cvt_tf32(v.x * INV_SCALE);
        v.y = cvt_tf32(v.y * INV_SCALE);
        v.z = cvt_tf32(v.z * INV_SCALE);
        v.w = cvt_tf32(v.w * INV_SCALE);
        *(float4*)&Ss[r * PK + 4 * c] = v;
    }
    __syncthreads();

    // ---- load Q fragments into registers (10 k-steps x 4 regs) ----
    uint32_t qf[10][4];
    {
        int r0 = (16 * w + g) * PK;
        int r1 = (16 * w + g + 8) * PK;
        #pragma unroll
        for (int s = 0; s < 10; s++) {
            qf[s][0] = __float_as_uint(Ss[r0 + 8 * s + t]);
            qf[s][1] = __float_as_uint(Ss[r1 + 8 * s + t]);
            qf[s][2] = __float_as_uint(Ss[r0 + 8 * s + t + 4]);
            qf[s][3] = __float_as_uint(Ss[r1 + 8 * s + t + 4]);
        }
    }

    float o[10][4];
    #pragma unroll
    for (int n = 0; n < 10; n++)
        #pragma unroll
        for (int j = 0; j < 4; j++) o[n][j] = 0.f;
    float m0 = -3.0e38f, m1 = -3.0e38f, l0 = 0.f, l1 = 0.f;

    for (int kt = 0; kt < SEQ / 128; kt++) {
        __syncthreads();   // prev iter done reading Ks/Vs; Q frags loaded
        int k0 = kt * 128;
        const float* kg = g_qkv + (size_t)k0 * QKVN + HIDDEN     + h * HD;
        const float* vg = g_qkv + (size_t)k0 * QKVN + 2 * HIDDEN + h * HD;
        for (int i = tid; i < 128 * 20; i += 256) {
            int r = i / 20, c = i % 20;
            float4 a = *(const float4*)&kg[(size_t)r * QKVN + 4 * c];
            a.x = cvt_tf32(a.x); a.y = cvt_tf32(a.y);
            a.z = cvt_tf32(a.z); a.w = cvt_tf32(a.w);
            *(float4*)&Ks[r * PK + 4 * c] = a;
            float4 b = *(const float4*)&vg[(size_t)r * QKVN + 4 * c];
            b.x = cvt_tf32(b.x); b.y = cvt_tf32(b.y);
            b.z = cvt_tf32(b.z); b.w = cvt_tf32(b.w);
            *(float4*)&Vs[r * PVp + 4 * c] = b;
        }
        __syncthreads();

        // ---- S = Q K^T : 16 n-tiles x 10 k-steps ----
        float sacc[16][4];
        #pragma unroll
        for (int n = 0; n < 16; n++)
            #pragma unroll
            for (int j = 0; j < 4; j++) sacc[n][j] = 0.f;

        #pragma unroll
        for (int s = 0; s < 10; s++) {
            #pragma unroll
            for (int nt = 0; nt < 16; nt++) {
                uint32_t b0 = __float_as_uint(Ks[(8 * nt + g) * PK + 8 * s + t]);
                uint32_t b1 = __float_as_uint(Ks[(8 * nt + g) * PK + 8 * s + t + 4]);
                mma_tf32(sacc[nt], qf[s][0], qf[s][1], qf[s][2], qf[s][3], b0, b1);
            }
        }

        // ---- online softmax (rows g and g+8 of this warp's slab) ----
        float rmax0 = sacc[0][0], rmax1 = sacc[0][2];
        #pragma unroll
        for (int nt = 0; nt < 16; nt++) {
            rmax0 = fmaxf(rmax0, fmaxf(sacc[nt][0], sacc[nt][1]));
            rmax1 = fmaxf(rmax1, fmaxf(sacc[nt][2], sacc[nt][3]));
        }
        rmax0 = fmaxf(rmax0, __shfl_xor_sync(0xffffffffu, rmax0, 1));
        rmax0 = fmaxf(rmax0, __shfl_xor_sync(0xffffffffu, rmax0, 2));
        rmax1 = fmaxf(rmax1, __shfl_xor_sync(0xffffffffu, rmax1, 1));
        rmax1 = fmaxf(rmax1, __shfl_xor_sync(0xffffffffu, rmax1, 2));

        float mn0 = fmaxf(m0, rmax0), mn1 = fmaxf(m1, rmax1);
        float alpha0 = __expf(m0 - mn0), alpha1 = __expf(m1 - mn1);
        m0 = mn0; m1 = mn1;

        float rs0 = 0.f, rs1 = 0.f;
        int pr0 = (16 * w + g) * PS;
        int pr1 = (16 * w + g + 8) * PS;
        #pragma unroll
        for (int nt = 0; nt < 16; nt++) {
            float p0 = __expf(sacc[nt][0] - mn0);
            float p1 = __expf(sacc[nt][1] - mn0);
            float p2 = __expf(sacc[nt][2] - mn1);
            float p3 = __expf(sacc[nt][3] - mn1);
            rs0 += p0 + p1;
            rs1 += p2 + p3;
            float2 u0 = make_float2(cvt_tf32(p0), cvt_tf32(p1));
            float2 u1 = make_float2(cvt_tf32(p2), cvt_tf32(p3));
            *(float2*)&Ss[pr0 + 8 * nt + 2 * t] = u0;
            *(float2*)&Ss[pr1 + 8 * nt + 2 * t] = u1;
        }
        rs0 += __shfl_xor_sync(0xffffffffu, rs0, 1);
        rs0 += __shfl_xor_sync(0xffffffffu, rs0, 2);
        rs1 += __shfl_xor_sync(0xffffffffu, rs1, 1);
        rs1 += __shfl_xor_sync(0xffffffffu, rs1, 2);
        l0 = l0 * alpha0 + rs0;
        l1 = l1 * alpha1 + rs1;

        #pragma unroll
        for (int n = 0; n < 10; n++) {
            o[n][0] *= alpha0; o[n][1] *= alpha0;
            o[n][2] *= alpha1; o[n][3] *= alpha1;
        }
        __syncwarp();   // P slab written/read within this warp only

        // ---- O += P V : 16 k-steps (keys) x 10 n-tiles (dims) ----
        #pragma unroll
        for (int s = 0; s < 16; s++) {
            uint32_t a0 = __float_as_uint(Ss[pr0 + 8 * s + t]);
            uint32_t a1 = __float_as_uint(Ss[pr1 + 8 * s + t]);
            uint32_t a2 = __float_as_uint(Ss[pr0 + 8 * s + t + 4]);
            uint32_t a3 = __float_as_uint(Ss[pr1 + 8 * s + t + 4]);
            #pragma unroll
            for (int nt = 0; nt < 10; nt++) {
                uint32_t b0 = __float_as_uint(Vs[(8 * s + t) * PVp + 8 * nt + g]);
                uint32_t b1 = __float_as_uint(Vs[(8 * s + t + 4) * PVp + 8 * nt + g]);
                mma_tf32(o[nt], a0, a1, a2, a3, b0, b1);
            }
        }
        __syncwarp();   // PV reads of Ss done before next tile's P writes
    }

    // ---- epilogue ----
    float il0 = 1.0f / l0, il1 = 1.0f / l1;
    size_t r0 = (size_t)(q0 + 16 * w + g);
    size_t r1 = r0 + 8;
    float* og0 = g_attn + r0 * HIDDEN + h * HD;
    float* og1 = g_attn + r1 * HIDDEN + h * HD;
    #pragma unroll
    for (int nt = 0; nt < 10; nt++) {
        *(float2*)&og0[8 * nt + 2 * t] = make_float2(o[nt][0] * il0, o[nt][1] * il0);
        *(float2*)&og1[8 * nt + 2 * t] = make_float2(o[nt][2] * il1, o[nt][3] * il1);
    }
}

// =====================================================================
extern "C" void kernel_launch(void* const* d_in, const int* in_sizes, int n_in,
                              void* d_out, int out_size)
{
    const float* x      = (const float*)d_in[0];
    const float* cosE   = (const float*)d_in[1];
    const float* sinE   = (const float*)d_in[2];
    const float* w_qkv  = (const float*)d_in[3];
    const float* b_qkv  = (const float*)d_in[4];
    const float* w_proj = (const float*)d_in[5];
    const float* b_proj = (const float*)d_in[6];
    float*       out    = (float*)d_out;

    float *qkv, *attn;
    cudaGetSymbolAddress((void**)&qkv,  g_qkv);
    cudaGetSymbolAddress((void**)&attn, g_attn);

    cudaFuncSetAttribute(flash_attn_tc,
                         cudaFuncAttributeMaxDynamicSharedMemorySize,
                         FA_SMEM_BYTES);

    // 1) QKV GEMM : [4096,1280] @ [1280,3840] + bias
    sgemm_bias<<<dim3(QKVN / 128, SEQ / 128), 256>>>(
        x, w_qkv, b_qkv, qkv, SEQ, QKVN, HIDDEN);

    // 2) RoPE on Q and K
    {
        int tot = 2 * SEQ * NH * (HD / 2);
        rope_kernel<<<(tot + 255) / 256, 256>>>(cosE, sinE);
    }

    // 3) tensor-core flash attention
    flash_attn_tc<<<dim3(SEQ / 128, NH), 256, FA_SMEM_BYTES>>>();

    // 4) output projection : [4096,1280] @ [1280,1280] + bias
    sgemm_bias<<<dim3(HIDDEN / 128, SEQ / 128), 256>>>(
        attn, w_proj, b_proj, out, SEQ, HIDDEN, HIDDEN);
}

// round 7
// speedup vs baseline: 1.0008x; 1.0008x over previous
#include <cuda_runtime.h>
#include <math.h>
#include <stdint.h>

#define SEQ    4096
#define NH     16
#define HD     80
#define HIDDEN 1280
#define QKVN   3840
#define INV_SCALE 0.11180339887498948f   // 1/sqrt(80)

// -------- scratch (no allocation allowed -> __device__ globals) --------
__device__ float g_qkv [SEQ * QKVN];    // 62.9 MB : [seq][3*hidden]
__device__ float g_attn[SEQ * HIDDEN];  // 21.0 MB : attention output

// =====================================================================
// SGEMM: C[M,N] = A[M,K] @ B[K,N] + bias[N]   (fp32, 128x128x8)
// =====================================================================
__global__ void __launch_bounds__(256)
sgemm_bias(const float* __restrict__ A, const float* __restrict__ B,
           const float* __restrict__ bias, float* __restrict__ C,
           int M, int N, int K)
{
    const int BM = 128, BN = 128, BK = 8, TM = 8, TN = 8;
    __shared__ float As[BK][BM];
    __shared__ float Bs[BK][BN];

    int tid = threadIdx.x;
    int tx = tid % 16;
    int ty = tid / 16;
    int bx = blockIdx.x, by = blockIdx.y;

    const float* Ab = A + (size_t)by * BM * K;
    const float* Bb = B + (size_t)bx * BN;

    int arow = tid >> 1;
    int acol = (tid & 1) * 4;
    int brow = tid >> 5;
    int bcol = (tid & 31) * 4;

    float acc[TM][TN];
    #pragma unroll
    for (int i = 0; i < TM; i++)
        #pragma unroll
        for (int j = 0; j < TN; j++) acc[i][j] = 0.f;

    for (int k0 = 0; k0 < K; k0 += BK) {
        float4 a4 = *(const float4*)&Ab[(size_t)arow * K + k0 + acol];
        As[acol + 0][arow] = a4.x;
        As[acol + 1][arow] = a4.y;
        As[acol + 2][arow] = a4.z;
        As[acol + 3][arow] = a4.w;
        float4 b4 = *(const float4*)&Bb[(size_t)(k0 + brow) * N + bcol];
        *(float4*)&Bs[brow][bcol] = b4;
        __syncthreads();

        #pragma unroll
        for (int k = 0; k < BK; k++) {
            float ra[TM], rb[TN];
            *(float4*)&ra[0] = *(const float4*)&As[k][ty * TM];
            *(float4*)&ra[4] = *(const float4*)&As[k][ty * TM + 4];
            *(float4*)&rb[0] = *(const float4*)&Bs[k][tx * TN];
            *(float4*)&rb[4] = *(const float4*)&Bs[k][tx * TN + 4];
            #pragma unroll
            for (int i = 0; i < TM; i++)
                #pragma unroll
                for (int j = 0; j < TN; j++)
                    acc[i][j] = fmaf(ra[i], rb[j], acc[i][j]);
        }
        __syncthreads();
    }

    #pragma unroll
    for (int i = 0; i < TM; i++) {
        size_t row = (size_t)by * BM + ty * TM + i;
        #pragma unroll
        for (int j = 0; j < TN; j += 4) {
            int col = bx * BN + tx * TN + j;
            float4 c4;
            c4.x = acc[i][j + 0] + bias[col + 0];
            c4.y = acc[i][j + 1] + bias[col + 1];
            c4.z = acc[i][j + 2] + bias[col + 2];
            c4.w = acc[i][j + 3] + bias[col + 3];
            *(float4*)&C[row * N + col] = c4;
        }
    }
}

// =====================================================================
// RoPE in-place on Q and K halves of g_qkv.
// =====================================================================
__global__ void rope_kernel(const float* __restrict__ cosE,
                            const float* __restrict__ sinE)
{
    int idx = blockIdx.x * blockDim.x + threadIdx.x;
    const int TOT = 2 * SEQ * NH * (HD / 2);
    if (idx >= TOT) return;
    int d    = idx % 40;
    int h    = (idx / 40) % NH;
    int s    = (idx / (40 * NH)) % SEQ;
    int part = idx / (40 * NH * SEQ);

    float* p = g_qkv + (size_t)s * QKVN + part * HIDDEN + h * HD;
    float t1 = p[d], t2 = p[d + 40];
    float c1 = cosE[s * HD + d],      s1 = sinE[s * HD + d];
    float c2 = cosE[s * HD + d + 40], s2 = sinE[s * HD + d + 40];
    p[d]      = t1 * c1 - t2 * s1;
    p[d + 40] = t2 * c2 + t1 * s2;
}

// =====================================================================
// TF32 tensor-core flash attention.
// grid=(SEQ/128, NH), 256 threads = 8 warps; each warp owns 16 query rows.
// mma.sync.m16n8k8 tf32. Q fragments register-resident across KV loop.
// Smem: Ks[128][84], Vs[128][88], Ss[128][132] (pads = conflict-free frags).
// =====================================================================
#define PK 84
#define PVp 88
#define PS 132
#define FA_SMEM_BYTES ((128*PK + 128*PVp + 128*PS) * 4)

__device__ __forceinline__ float cvt_tf32(float x) {
    uint32_t u;
    asm("cvt.rna.tf32.f32 %0, %1;" : "=r"(u) : "f"(x));
    return __uint_as_float(u);
}

__device__ __forceinline__ void mma_tf32(float* c,
    uint32_t a0, uint32_t a1, uint32_t a2, uint32_t a3,
    uint32_t b0, uint32_t b1)
{
    asm volatile(
        "mma.sync.aligned.m16n8k8.row.col.f32.tf32.tf32.f32 "
        "{%0,%1,%2,%3}, {%4,%5,%6,%7}, {%8,%9}, {%0,%1,%2,%3};\n"
        : "+f"(c[0]), "+f"(c[1]), "+f"(c[2]), "+f"(c[3])
        : "r"(a0), "r"(a1), "r"(a2), "r"(a3), "r"(b0), "r"(b1));
}

__global__ void __launch_bounds__(256, 1)
flash_attn_tc()
{
    extern __shared__ float sm[];
    float* Ks = sm;                    // [128][PK]
    float* Vs = Ks + 128 * PK;         // [128][PVp]
    float* Ss = Vs + 128 * PVp;        // [128][PS]; also Q staging (pad PK)

    int tid  = threadIdx.x;
    int lane = tid & 31;
    int w    = tid >> 5;               // warp 0..7 -> rows 16w..16w+15
    int g    = lane >> 2;              // group id (row within octet)
    int t    = lane & 3;               // thread in group
    int h    = blockIdx.y;
    int q0   = blockIdx.x * 128;

    // ---- stage Q (scaled + tf32-rounded) into Ss with pad PK ----
    const float* qg = g_qkv + (size_t)q0 * QKVN + h * HD;
    for (int i = tid; i < 128 * 20; i += 256) {
        int r = i / 20, c = i % 20;
        float4 v = *(const float4*)&qg[(size_t)r * QKVN + 4 * c];
        v.x = cvt_tf32(v.x * INV_SCALE);
        v.y = cvt_tf32(v.y * INV_SCALE);
        v.z = cvt_tf32(v.z * INV_SCALE);
        v.w = cvt_tf32(v.w * INV_SCALE);
        *(float4*)&Ss[r * PK + 4 * c] = v;
    }
    __syncthreads();

    // ---- load Q fragments into registers (10 k-steps x 4 regs) ----
    uint32_t qf[10][4];
    {
        int r0 = (16 * w + g) * PK;
        int r1 = (16 * w + g + 8) * PK;
        #pragma unroll
        for (int s = 0; s < 10; s++) {
            qf[s][0] = __float_as_uint(Ss[r0 + 8 * s + t]);
            qf[s][1] = __float_as_uint(Ss[r1 + 8 * s + t]);
            qf[s][2] = __float_as_uint(Ss[r0 + 8 * s + t + 4]);
            qf[s][3] = __float_as_uint(Ss[r1 + 8 * s + t + 4]);
        }
    }

    float o[10][4];
    #pragma unroll
    for (int n = 0; n < 10; n++)
        #pragma unroll
        for (int j = 0; j < 4; j++) o[n][j] = 0.f;
    float m0 = -3.0e38f, m1 = -3.0e38f, l0 = 0.f, l1 = 0.f;

    for (int kt = 0; kt < SEQ / 128; kt++) {
        __syncthreads();   // prev iter done reading Ks/Vs; Q frags loaded
        int k0 = kt * 128;
        const float* kg = g_qkv + (size_t)k0 * QKVN + HIDDEN     + h * HD;
        const float* vg = g_qkv + (size_t)k0 * QKVN + 2 * HIDDEN + h * HD;
        for (int i = tid; i < 128 * 20; i += 256) {
            int r = i / 20, c = i % 20;
            float4 a = *(const float4*)&kg[(size_t)r * QKVN + 4 * c];
            a.x = cvt_tf32(a.x); a.y = cvt_tf32(a.y);
            a.z = cvt_tf32(a.z); a.w = cvt_tf32(a.w);
            *(float4*)&Ks[r * PK + 4 * c] = a;
            float4 b = *(const float4*)&vg[(size_t)r * QKVN + 4 * c];
            b.x = cvt_tf32(b.x); b.y = cvt_tf32(b.y);
            b.z = cvt_tf32(b.z); b.w = cvt_tf32(b.w);
            *(float4*)&Vs[r * PVp + 4 * c] = b;
        }
        __syncthreads();

        // ---- S = Q K^T : 16 n-tiles x 10 k-steps ----
        float sacc[16][4];
        #pragma unroll
        for (int n = 0; n < 16; n++)
            #pragma unroll
            for (int j = 0; j < 4; j++) sacc[n][j] = 0.f;

        #pragma unroll
        for (int s = 0; s < 10; s++) {
            #pragma unroll
            for (int nt = 0; nt < 16; nt++) {
                uint32_t b0 = __float_as_uint(Ks[(8 * nt + g) * PK + 8 * s + t]);
                uint32_t b1 = __float_as_uint(Ks[(8 * nt + g) * PK + 8 * s + t + 4]);
                mma_tf32(sacc[nt], qf[s][0], qf[s][1], qf[s][2], qf[s][3], b0, b1);
            }
        }

        // ---- online softmax (rows g and g+8 of this warp's slab) ----
        float rmax0 = sacc[0][0], rmax1 = sacc[0][2];
        #pragma unroll
        for (int nt = 0; nt < 16; nt++) {
            rmax0 = fmaxf(rmax0, fmaxf(sacc[nt][0], sacc[nt][1]));
            rmax1 = fmaxf(rmax1, fmaxf(sacc[nt][2], sacc[nt][3]));
        }
        rmax0 = fmaxf(rmax0, __shfl_xor_sync(0xffffffffu, rmax0, 1));
        rmax0 = fmaxf(rmax0, __shfl_xor_sync(0xffffffffu, rmax0, 2));
        rmax1 = fmaxf(rmax1, __shfl_xor_sync(0xffffffffu, rmax1, 1));
        rmax1 = fmaxf(rmax1, __shfl_xor_sync(0xffffffffu, rmax1, 2));

        float mn0 = fmaxf(m0, rmax0), mn1 = fmaxf(m1, rmax1);
        float alpha0 = __expf(m0 - mn0), alpha1 = __expf(m1 - mn1);
        m0 = mn0; m1 = mn1;

        float rs0 = 0.f, rs1 = 0.f;
        int pr0 = (16 * w + g) * PS;
        int pr1 = (16 * w + g + 8) * PS;
        #pragma unroll
        for (int nt = 0; nt < 16; nt++) {
            float p0 = __expf(sacc[nt][0] - mn0);
            float p1 = __expf(sacc[nt][1] - mn0);
            float p2 = __expf(sacc[nt][2] - mn1);
            float p3 = __expf(sacc[nt][3] - mn1);
            rs0 += p0 + p1;
            rs1 += p2 + p3;
            float2 u0 = make_float2(cvt_tf32(p0), cvt_tf32(p1));
            float2 u1 = make_float2(cvt_tf32(p2), cvt_tf32(p3));
            *(float2*)&Ss[pr0 + 8 * nt + 2 * t] = u0;
            *(float2*)&Ss[pr1 + 8 * nt + 2 * t] = u1;
        }
        rs0 += __shfl_xor_sync(0xffffffffu, rs0, 1);
        rs0 += __shfl_xor_sync(0xffffffffu, rs0, 2);
        rs1 += __shfl_xor_sync(0xffffffffu, rs1, 1);
        rs1 += __shfl_xor_sync(0xffffffffu, rs1, 2);
        l0 = l0 * alpha0 + rs0;
        l1 = l1 * alpha1 + rs1;

        #pragma unroll
        for (int n = 0; n < 10; n++) {
            o[n][0] *= alpha0; o[n][1] *= alpha0;
            o[n][2] *= alpha1; o[n][3] *= alpha1;
        }
        __syncwarp();   // P slab written/read within this warp only

        // ---- O += P V : 16 k-steps (keys) x 10 n-tiles (dims) ----
        #pragma unroll
        for (int s = 0; s < 16; s++) {
            uint32_t a0 = __float_as_uint(Ss[pr0 + 8 * s + t]);
            uint32_t a1 = __float_as_uint(Ss[pr1 + 8 * s + t]);
            uint32_t a2 = __float_as_uint(Ss[pr0 + 8 * s + t + 4]);
            uint32_t a3 = __float_as_uint(Ss[pr1 + 8 * s + t + 4]);
            #pragma unroll
            for (int nt = 0; nt < 10; nt++) {
                uint32_t b0 = __float_as_uint(Vs[(8 * s + t) * PVp + 8 * nt + g]);
                uint32_t b1 = __float_as_uint(Vs[(8 * s + t + 4) * PVp + 8 * nt + g]);
                mma_tf32(o[nt], a0, a1, a2, a3, b0, b1);
            }
        }
        __syncwarp();   // PV reads of Ss done before next tile's P writes
    }

    // ---- epilogue ----
    float il0 = 1.0f / l0, il1 = 1.0f / l1;
    size_t r0 = (size_t)(q0 + 16 * w + g);
    size_t r1 = r0 + 8;
    float* og0 = g_attn + r0 * HIDDEN + h * HD;
    float* og1 = g_attn + r1 * HIDDEN + h * HD;
    #pragma unroll
    for (int nt = 0; nt < 10; nt++) {
        *(float2*)&og0[8 * nt + 2 * t] = make_float2(o[nt][0] * il0, o[nt][1] * il0);
        *(float2*)&og1[8 * nt + 2 * t] = make_float2(o[nt][2] * il1, o[nt][3] * il1);
    }
}

// =====================================================================
extern "C" void kernel_launch(void* const* d_in, const int* in_sizes, int n_in,
                              void* d_out, int out_size)
{
    const float* x      = (const float*)d_in[0];
    const float* cosE   = (const float*)d_in[1];
    const float* sinE   = (const float*)d_in[2];
    const float* w_qkv  = (const float*)d_in[3];
    const float* b_qkv  = (const float*)d_in[4];
    const float* w_proj = (const float*)d_in[5];
    const float* b_proj = (const float*)d_in[6];
    float*       out    = (float*)d_out;

    float *qkv, *attn;
    cudaGetSymbolAddress((void**)&qkv,  g_qkv);
    cudaGetSymbolAddress((void**)&attn, g_attn);

    cudaFuncSetAttribute(flash_attn_tc,
                         cudaFuncAttributeMaxDynamicSharedMemorySize,
                         FA_SMEM_BYTES);

    // 1) QKV GEMM : [4096,1280] @ [1280,3840] + bias
    sgemm_bias<<<dim3(QKVN / 128, SEQ / 128), 256>>>(
        x, w_qkv, b_qkv, qkv, SEQ, QKVN, HIDDEN);

    // 2) RoPE on Q and K
    {
        int tot = 2 * SEQ * NH * (HD / 2);
        rope_kernel<<<(tot + 255) / 256, 256>>>(cosE, sinE);
    }

    // 3) tensor-core flash attention
    flash_attn_tc<<<dim3(SEQ / 128, NH), 256, FA_SMEM_BYTES>>>();

    // 4) output projection : [4096,1280] @ [1280,1280] + bias
    sgemm_bias<<<dim3(HIDDEN / 128, SEQ / 128), 256>>>(
        attn, w_proj, b_proj, out, SEQ, HIDDEN, HIDDEN);
}

// round 8
// speedup vs baseline: 1.7603x; 1.7589x over previous
#include <cuda_runtime.h>
#include <math.h>
#include <stdint.h>

#define SEQ    4096
#define NH     16
#define HD     80
#define HIDDEN 1280
#define QKVN   3840
#define INV_SCALE 0.11180339887498948f   // 1/sqrt(80)

// -------- scratch (no allocation allowed -> __device__ globals) --------
__device__ float g_qkv [SEQ * QKVN];    // 62.9 MB : [seq][3*hidden]
__device__ float g_attn[SEQ * HIDDEN];  // 21.0 MB : attention output

// =====================================================================
// common TF32 helpers
// =====================================================================
__device__ __forceinline__ float cvt_tf32(float x) {
    uint32_t u;
    asm("cvt.rna.tf32.f32 %0, %1;" : "=r"(u) : "f"(x));
    return __uint_as_float(u);
}

__device__ __forceinline__ void mma_tf32(float* c,
    uint32_t a0, uint32_t a1, uint32_t a2, uint32_t a3,
    uint32_t b0, uint32_t b1)
{
    asm volatile(
        "mma.sync.aligned.m16n8k8.row.col.f32.tf32.tf32.f32 "
        "{%0,%1,%2,%3}, {%4,%5,%6,%7}, {%8,%9}, {%0,%1,%2,%3};\n"
        : "+f"(c[0]), "+f"(c[1]), "+f"(c[2]), "+f"(c[3])
        : "r"(a0), "r"(a1), "r"(a2), "r"(a3), "r"(b0), "r"(b1));
}

// =====================================================================
// TF32 tensor-core GEMM: C[M,N] = A[M,K] @ B[K,N] + bias
// 128x128 CTA tile, BK=16, 256 threads = 8 warps (2x4), warp = 64x32.
// As[m][k] pad 20 (a-frag lanes g*20+t : conflict-free)
// Bs[k][n] pad 136 (b-frag lanes t*8+g : conflict-free)
// =====================================================================
#define GAPAD 20
#define GBPAD 136

__global__ void __launch_bounds__(256, 2)
sgemm_tf32(const float* __restrict__ A, const float* __restrict__ B,
           const float* __restrict__ bias, float* __restrict__ C,
           int M, int N, int K)
{
    __shared__ float As[128 * GAPAD];
    __shared__ float Bs[16 * GBPAD];

    int tid  = threadIdx.x;
    int lane = tid & 31;
    int w    = tid >> 5;
    int g    = lane >> 2;
    int t    = lane & 3;
    int wr   = w >> 2;               // 0..1
    int wc   = w & 3;                // 0..3
    int bx = blockIdx.x, by = blockIdx.y;

    const float* Ab = A + (size_t)by * 128 * K;
    const float* Bb = B + (size_t)bx * 128;

    float acc[4][4][4];
    #pragma unroll
    for (int mt = 0; mt < 4; mt++)
        #pragma unroll
        for (int nt = 0; nt < 4; nt++)
            #pragma unroll
            for (int j = 0; j < 4; j++) acc[mt][nt][j] = 0.f;

    for (int k0 = 0; k0 < K; k0 += 16) {
        // ---- stage A (128x16) and B (16x128), tf32-rounded ----
        #pragma unroll
        for (int it = 0; it < 2; it++) {
            int c = tid + it * 256;          // 0..511 float4 chunks
            int arow = c >> 2, acolq = c & 3;
            float4 a4 = *(const float4*)&Ab[(size_t)arow * K + k0 + 4 * acolq];
            a4.x = cvt_tf32(a4.x); a4.y = cvt_tf32(a4.y);
            a4.z = cvt_tf32(a4.z); a4.w = cvt_tf32(a4.w);
            *(float4*)&As[arow * GAPAD + 4 * acolq] = a4;

            int krow = c >> 5, nq = c & 31;
            float4 b4 = *(const float4*)&Bb[(size_t)(k0 + krow) * N + 4 * nq];
            b4.x = cvt_tf32(b4.x); b4.y = cvt_tf32(b4.y);
            b4.z = cvt_tf32(b4.z); b4.w = cvt_tf32(b4.w);
            *(float4*)&Bs[krow * GBPAD + 4 * nq] = b4;
        }
        __syncthreads();

        #pragma unroll
        for (int s = 0; s < 2; s++) {
            uint32_t af[4][4], bf[4][2];
            #pragma unroll
            for (int mt = 0; mt < 4; mt++) {
                int mrow = wr * 64 + 16 * mt;
                af[mt][0] = __float_as_uint(As[(mrow + g    ) * GAPAD + 8 * s + t    ]);
                af[mt][1] = __float_as_uint(As[(mrow + g + 8) * GAPAD + 8 * s + t    ]);
                af[mt][2] = __float_as_uint(As[(mrow + g    ) * GAPAD + 8 * s + t + 4]);
                af[mt][3] = __float_as_uint(As[(mrow + g + 8) * GAPAD + 8 * s + t + 4]);
            }
            #pragma unroll
            for (int nt = 0; nt < 4; nt++) {
                int nb = wc * 32 + 8 * nt;
                bf[nt][0] = __float_as_uint(Bs[(8 * s + t    ) * GBPAD + nb + g]);
                bf[nt][1] = __float_as_uint(Bs[(8 * s + t + 4) * GBPAD + nb + g]);
            }
            #pragma unroll
            for (int mt = 0; mt < 4; mt++)
                #pragma unroll
                for (int nt = 0; nt < 4; nt++)
                    mma_tf32(acc[mt][nt], af[mt][0], af[mt][1], af[mt][2], af[mt][3],
                             bf[nt][0], bf[nt][1]);
        }
        __syncthreads();
    }

    // ---- epilogue ----
    #pragma unroll
    for (int mt = 0; mt < 4; mt++) {
        size_t row0 = (size_t)by * 128 + wr * 64 + 16 * mt + g;
        #pragma unroll
        for (int nt = 0; nt < 4; nt++) {
            int col = bx * 128 + wc * 32 + 8 * nt + 2 * t;
            float b0 = bias[col], b1 = bias[col + 1];
            *(float2*)&C[row0 * N + col] =
                make_float2(acc[mt][nt][0] + b0, acc[mt][nt][1] + b1);
            *(float2*)&C[(row0 + 8) * N + col] =
                make_float2(acc[mt][nt][2] + b0, acc[mt][nt][3] + b1);
        }
    }
}

// =====================================================================
// RoPE in-place on Q and K halves of g_qkv.
// =====================================================================
__global__ void rope_kernel(const float* __restrict__ cosE,
                            const float* __restrict__ sinE)
{
    int idx = blockIdx.x * blockDim.x + threadIdx.x;
    const int TOT = 2 * SEQ * NH * (HD / 2);
    if (idx >= TOT) return;
    int d    = idx % 40;
    int h    = (idx / 40) % NH;
    int s    = (idx / (40 * NH)) % SEQ;
    int part = idx / (40 * NH * SEQ);

    float* p = g_qkv + (size_t)s * QKVN + part * HIDDEN + h * HD;
    float t1 = p[d], t2 = p[d + 40];
    float c1 = cosE[s * HD + d],      s1 = sinE[s * HD + d];
    float c2 = cosE[s * HD + d + 40], s2 = sinE[s * HD + d + 40];
    p[d]      = t1 * c1 - t2 * s1;
    p[d + 40] = t2 * c2 + t1 * s2;
}

// =====================================================================
// TF32 flash attention, BM=64 q-rows x BN=64 keys, 128 threads (4 warps),
// 61 KB smem -> 3 CTAs/SM for cross-CTA latency hiding.
// Ks[64][84] (doubles as Q staging), Vs[64][88], Sp[64][68].
// =====================================================================
#define FBM 64
#define FBN 64
#define QPAD 84
#define VPAD 88
#define SPAD 68
#define FA_SMEM_BYTES ((FBN*QPAD + FBN*VPAD + FBM*SPAD) * 4)   // 61440

__global__ void __launch_bounds__(128, 3)
flash_attn_tc()
{
    extern __shared__ float sm[];
    float* Ks = sm;                    // [64][QPAD]  (first: staged Q)
    float* Vs = Ks + FBN * QPAD;       // [64][VPAD]
    float* Sp = Vs + FBN * VPAD;       // [64][SPAD]  (P tile)

    int tid  = threadIdx.x;
    int lane = tid & 31;
    int w    = tid >> 5;               // warp 0..3 -> q rows 16w..16w+15
    int g    = lane >> 2;
    int t    = lane & 3;
    int h    = blockIdx.y;
    int q0   = blockIdx.x * FBM;

    // ---- stage Q (scaled + tf32) into Ks ----
    const float* qg = g_qkv + (size_t)q0 * QKVN + h * HD;
    for (int i = tid; i < FBM * 20; i += 128) {
        int r = i / 20, c = i % 20;
        float4 v = *(const float4*)&qg[(size_t)r * QKVN + 4 * c];
        v.x = cvt_tf32(v.x * INV_SCALE);
        v.y = cvt_tf32(v.y * INV_SCALE);
        v.z = cvt_tf32(v.z * INV_SCALE);
        v.w = cvt_tf32(v.w * INV_SCALE);
        *(float4*)&Ks[r * QPAD + 4 * c] = v;
    }
    __syncthreads();

    // ---- Q fragments -> registers ----
    uint32_t qf[10][4];
    {
        int r0 = (16 * w + g) * QPAD;
        int r1 = (16 * w + g + 8) * QPAD;
        #pragma unroll
        for (int s = 0; s < 10; s++) {
            qf[s][0] = __float_as_uint(Ks[r0 + 8 * s + t]);
            qf[s][1] = __float_as_uint(Ks[r1 + 8 * s + t]);
            qf[s][2] = __float_as_uint(Ks[r0 + 8 * s + t + 4]);
            qf[s][3] = __float_as_uint(Ks[r1 + 8 * s + t + 4]);
        }
    }

    float o[10][4];
    #pragma unroll
    for (int n = 0; n < 10; n++)
        #pragma unroll
        for (int j = 0; j < 4; j++) o[n][j] = 0.f;
    float m0 = -3.0e38f, m1 = -3.0e38f, l0 = 0.f, l1 = 0.f;

    int pr0 = (16 * w + g) * SPAD;
    int pr1 = (16 * w + g + 8) * SPAD;

    for (int kt = 0; kt < SEQ / FBN; kt++) {
        __syncthreads();               // Ks (Q/prev K) and Vs free to overwrite
        int k0 = kt * FBN;
        const float* kg = g_qkv + (size_t)k0 * QKVN + HIDDEN     + h * HD;
        const float* vg = g_qkv + (size_t)k0 * QKVN + 2 * HIDDEN + h * HD;
        for (int i = tid; i < FBN * 20; i += 128) {
            int r = i / 20, c = i % 20;
            float4 a = *(const float4*)&kg[(size_t)r * QKVN + 4 * c];
            a.x = cvt_tf32(a.x); a.y = cvt_tf32(a.y);
            a.z = cvt_tf32(a.z); a.w = cvt_tf32(a.w);
            *(float4*)&Ks[r * QPAD + 4 * c] = a;
            float4 b = *(const float4*)&vg[(size_t)r * QKVN + 4 * c];
            b.x = cvt_tf32(b.x); b.y = cvt_tf32(b.y);
            b.z = cvt_tf32(b.z); b.w = cvt_tf32(b.w);
            *(float4*)&Vs[r * VPAD + 4 * c] = b;
        }
        __syncthreads();

        // ---- S = Q K^T : 8 n-tiles x 10 k-steps ----
        float sacc[8][4];
        #pragma unroll
        for (int n = 0; n < 8; n++)
            #pragma unroll
            for (int j = 0; j < 4; j++) sacc[n][j] = 0.f;

        #pragma unroll
        for (int s = 0; s < 10; s++) {
            #pragma unroll
            for (int nt = 0; nt < 8; nt++) {
                uint32_t b0 = __float_as_uint(Ks[(8 * nt + g) * QPAD + 8 * s + t]);
                uint32_t b1 = __float_as_uint(Ks[(8 * nt + g) * QPAD + 8 * s + t + 4]);
                mma_tf32(sacc[nt], qf[s][0], qf[s][1], qf[s][2], qf[s][3], b0, b1);
            }
        }

        // ---- online softmax ----
        float rmax0 = sacc[0][0], rmax1 = sacc[0][2];
        #pragma unroll
        for (int nt = 0; nt < 8; nt++) {
            rmax0 = fmaxf(rmax0, fmaxf(sacc[nt][0], sacc[nt][1]));
            rmax1 = fmaxf(rmax1, fmaxf(sacc[nt][2], sacc[nt][3]));
        }
        rmax0 = fmaxf(rmax0, __shfl_xor_sync(0xffffffffu, rmax0, 1));
        rmax0 = fmaxf(rmax0, __shfl_xor_sync(0xffffffffu, rmax0, 2));
        rmax1 = fmaxf(rmax1, __shfl_xor_sync(0xffffffffu, rmax1, 1));
        rmax1 = fmaxf(rmax1, __shfl_xor_sync(0xffffffffu, rmax1, 2));

        float mn0 = fmaxf(m0, rmax0), mn1 = fmaxf(m1, rmax1);
        float alpha0 = __expf(m0 - mn0), alpha1 = __expf(m1 - mn1);
        m0 = mn0; m1 = mn1;

        float rs0 = 0.f, rs1 = 0.f;
        #pragma unroll
        for (int nt = 0; nt < 8; nt++) {
            float p0 = __expf(sacc[nt][0] - mn0);
            float p1 = __expf(sacc[nt][1] - mn0);
            float p2 = __expf(sacc[nt][2] - mn1);
            float p3 = __expf(sacc[nt][3] - mn1);
            rs0 += p0 + p1;
            rs1 += p2 + p3;
            *(float2*)&Sp[pr0 + 8 * nt + 2 * t] = make_float2(cvt_tf32(p0), cvt_tf32(p1));
            *(float2*)&Sp[pr1 + 8 * nt + 2 * t] = make_float2(cvt_tf32(p2), cvt_tf32(p3));
        }
        rs0 += __shfl_xor_sync(0xffffffffu, rs0, 1);
        rs0 += __shfl_xor_sync(0xffffffffu, rs0, 2);
        rs1 += __shfl_xor_sync(0xffffffffu, rs1, 1);
        rs1 += __shfl_xor_sync(0xffffffffu, rs1, 2);
        l0 = l0 * alpha0 + rs0;
        l1 = l1 * alpha1 + rs1;

        #pragma unroll
        for (int n = 0; n < 10; n++) {
            o[n][0] *= alpha0; o[n][1] *= alpha0;
            o[n][2] *= alpha1; o[n][3] *= alpha1;
        }
        __syncwarp();   // P slab is warp-private

        // ---- O += P V : 8 k-steps x 10 n-tiles ----
        #pragma unroll
        for (int s = 0; s < 8; s++) {
            uint32_t a0 = __float_as_uint(Sp[pr0 + 8 * s + t]);
            uint32_t a1 = __float_as_uint(Sp[pr1 + 8 * s + t]);
            uint32_t a2 = __float_as_uint(Sp[pr0 + 8 * s + t + 4]);
            uint32_t a3 = __float_as_uint(Sp[pr1 + 8 * s + t + 4]);
            #pragma unroll
            for (int nt = 0; nt < 10; nt++) {
                uint32_t b0 = __float_as_uint(Vs[(8 * s + t    ) * VPAD + 8 * nt + g]);
                uint32_t b1 = __float_as_uint(Vs[(8 * s + t + 4) * VPAD + 8 * nt + g]);
                mma_tf32(o[nt], a0, a1, a2, a3, b0, b1);
            }
        }
        __syncwarp();
    }

    // ---- epilogue ----
    float il0 = 1.0f / l0, il1 = 1.0f / l1;
    size_t r0 = (size_t)(q0 + 16 * w + g);
    float* og0 = g_attn + r0 * HIDDEN + h * HD;
    float* og1 = og0 + 8 * HIDDEN;
    #pragma unroll
    for (int nt = 0; nt < 10; nt++) {
        *(float2*)&og0[8 * nt + 2 * t] = make_float2(o[nt][0] * il0, o[nt][1] * il0);
        *(float2*)&og1[8 * nt + 2 * t] = make_float2(o[nt][2] * il1, o[nt][3] * il1);
    }
}

// =====================================================================
extern "C" void kernel_launch(void* const* d_in, const int* in_sizes, int n_in,
                              void* d_out, int out_size)
{
    const float* x      = (const float*)d_in[0];
    const float* cosE   = (const float*)d_in[1];
    const float* sinE   = (const float*)d_in[2];
    const float* w_qkv  = (const float*)d_in[3];
    const float* b_qkv  = (const float*)d_in[4];
    const float* w_proj = (const float*)d_in[5];
    const float* b_proj = (const float*)d_in[6];
    float*       out    = (float*)d_out;

    float *qkv, *attn;
    cudaGetSymbolAddress((void**)&qkv,  g_qkv);
    cudaGetSymbolAddress((void**)&attn, g_attn);

    cudaFuncSetAttribute(flash_attn_tc,
                         cudaFuncAttributeMaxDynamicSharedMemorySize,
                         FA_SMEM_BYTES);

    // 1) QKV GEMM : [4096,1280] @ [1280,3840] + bias   (TF32 tensor core)
    sgemm_tf32<<<dim3(QKVN / 128, SEQ / 128), 256>>>(
        x, w_qkv, b_qkv, qkv, SEQ, QKVN, HIDDEN);

    // 2) RoPE on Q and K
    {
        int tot = 2 * SEQ * NH * (HD / 2);
        rope_kernel<<<(tot + 255) / 256, 256>>>(cosE, sinE);
    }

    // 3) TF32 flash attention (64x64 tiles, 3 CTAs/SM)
    flash_attn_tc<<<dim3(SEQ / FBM, NH), 128, FA_SMEM_BYTES>>>();

    // 4) output projection : [4096,1280] @ [1280,1280] + bias (TF32)
    sgemm_tf32<<<dim3(HIDDEN / 128, SEQ / 128), 256>>>(
        attn, w_proj, b_proj, out, SEQ, HIDDEN, HIDDEN);
}

// round 9
// speedup vs baseline: 1.7748x; 1.0082x over previous
#include <cuda_runtime.h>
#include <math.h>
#include <stdint.h>

#define SEQ    4096
#define NH     16
#define HD     80
#define HIDDEN 1280
#define QKVN   3840
#define INV_SCALE 0.11180339887498948f   // 1/sqrt(80)

// -------- scratch (no allocation allowed -> __device__ globals) --------
__device__ float g_qkv [SEQ * QKVN];    // 62.9 MB : [seq][3*hidden]
__device__ float g_attn[SEQ * HIDDEN];  // 21.0 MB : attention output

// =====================================================================
// common TF32 helpers
// =====================================================================
__device__ __forceinline__ float cvt_tf32(float x) {
    uint32_t u;
    asm("cvt.rna.tf32.f32 %0, %1;" : "=r"(u) : "f"(x));
    return __uint_as_float(u);
}

__device__ __forceinline__ void mma_tf32(float* c,
    uint32_t a0, uint32_t a1, uint32_t a2, uint32_t a3,
    uint32_t b0, uint32_t b1)
{
    asm volatile(
        "mma.sync.aligned.m16n8k8.row.col.f32.tf32.tf32.f32 "
        "{%0,%1,%2,%3}, {%4,%5,%6,%7}, {%8,%9}, {%0,%1,%2,%3};\n"
        : "+f"(c[0]), "+f"(c[1]), "+f"(c[2]), "+f"(c[3])
        : "r"(a0), "r"(a1), "r"(a2), "r"(a3), "r"(b0), "r"(b1));
}

// =====================================================================
// TF32 tensor-core GEMM with double-buffered smem + register prefetch.
// 128x128 CTA tile, BK=16, 256 threads = 8 warps (2x4), warp = 64x32.
// =====================================================================
#define GAPAD 20
#define GBPAD 136
#define GA_FLOATS (128 * GAPAD)
#define GB_FLOATS (16 * GBPAD)

__global__ void __launch_bounds__(256, 2)
sgemm_tf32(const float* __restrict__ A, const float* __restrict__ B,
           const float* __restrict__ bias, float* __restrict__ C,
           int M, int N, int K)
{
    __shared__ float As[2][GA_FLOATS];
    __shared__ float Bs[2][GB_FLOATS];

    int tid  = threadIdx.x;
    int lane = tid & 31;
    int w    = tid >> 5;
    int g    = lane >> 2;
    int t    = lane & 3;
    int wr   = w >> 2;               // 0..1
    int wc   = w & 3;                // 0..3
    int bx = blockIdx.x, by = blockIdx.y;

    const float* Ab = A + (size_t)by * 128 * K;
    const float* Bb = B + (size_t)bx * 128;

    // staging maps (per "it" of 2)
    int arow[2], acolq[2], krow[2], nq[2];
    #pragma unroll
    for (int it = 0; it < 2; it++) {
        int c = tid + it * 256;
        arow[it] = c >> 2;  acolq[it] = c & 3;
        krow[it] = c >> 5;  nq[it]    = c & 31;
    }

    float acc[4][4][4];
    #pragma unroll
    for (int mt = 0; mt < 4; mt++)
        #pragma unroll
        for (int nt = 0; nt < 4; nt++)
            #pragma unroll
            for (int j = 0; j < 4; j++) acc[mt][nt][j] = 0.f;

    const int NIT = K / 16;

    // ---- prologue: stage slab 0 into buffer 0 ----
    #pragma unroll
    for (int it = 0; it < 2; it++) {
        float4 a4 = *(const float4*)&Ab[(size_t)arow[it] * K + 4 * acolq[it]];
        a4.x = cvt_tf32(a4.x); a4.y = cvt_tf32(a4.y);
        a4.z = cvt_tf32(a4.z); a4.w = cvt_tf32(a4.w);
        *(float4*)&As[0][arow[it] * GAPAD + 4 * acolq[it]] = a4;
        float4 b4 = *(const float4*)&Bb[(size_t)krow[it] * N + 4 * nq[it]];
        b4.x = cvt_tf32(b4.x); b4.y = cvt_tf32(b4.y);
        b4.z = cvt_tf32(b4.z); b4.w = cvt_tf32(b4.w);
        *(float4*)&Bs[0][krow[it] * GBPAD + 4 * nq[it]] = b4;
    }
    __syncthreads();

    #pragma unroll 1
    for (int i = 0; i < NIT; i++) {
        int cur = i & 1, nxt = cur ^ 1;
        const float* Ac = As[cur];
        const float* Bc = Bs[cur];

        // prefetch next slab into registers (latency hidden by mma below)
        float4 pa[2], pb[2];
        bool pf = (i + 1 < NIT);
        if (pf) {
            int k0 = (i + 1) * 16;
            #pragma unroll
            for (int it = 0; it < 2; it++) {
                pa[it] = *(const float4*)&Ab[(size_t)arow[it] * K + k0 + 4 * acolq[it]];
                pb[it] = *(const float4*)&Bb[(size_t)(k0 + krow[it]) * N + 4 * nq[it]];
            }
        }

        #pragma unroll
        for (int s = 0; s < 2; s++) {
            uint32_t af[4][4], bf[4][2];
            #pragma unroll
            for (int mt = 0; mt < 4; mt++) {
                int mrow = wr * 64 + 16 * mt;
                af[mt][0] = __float_as_uint(Ac[(mrow + g    ) * GAPAD + 8 * s + t    ]);
                af[mt][1] = __float_as_uint(Ac[(mrow + g + 8) * GAPAD + 8 * s + t    ]);
                af[mt][2] = __float_as_uint(Ac[(mrow + g    ) * GAPAD + 8 * s + t + 4]);
                af[mt][3] = __float_as_uint(Ac[(mrow + g + 8) * GAPAD + 8 * s + t + 4]);
            }
            #pragma unroll
            for (int nt = 0; nt < 4; nt++) {
                int nb = wc * 32 + 8 * nt;
                bf[nt][0] = __float_as_uint(Bc[(8 * s + t    ) * GBPAD + nb + g]);
                bf[nt][1] = __float_as_uint(Bc[(8 * s + t + 4) * GBPAD + nb + g]);
            }
            #pragma unroll
            for (int mt = 0; mt < 4; mt++)
                #pragma unroll
                for (int nt = 0; nt < 4; nt++)
                    mma_tf32(acc[mt][nt], af[mt][0], af[mt][1], af[mt][2], af[mt][3],
                             bf[nt][0], bf[nt][1]);
        }

        if (pf) {
            #pragma unroll
            for (int it = 0; it < 2; it++) {
                float4 a4 = pa[it];
                a4.x = cvt_tf32(a4.x); a4.y = cvt_tf32(a4.y);
                a4.z = cvt_tf32(a4.z); a4.w = cvt_tf32(a4.w);
                *(float4*)&As[nxt][arow[it] * GAPAD + 4 * acolq[it]] = a4;
                float4 b4 = pb[it];
                b4.x = cvt_tf32(b4.x); b4.y = cvt_tf32(b4.y);
                b4.z = cvt_tf32(b4.z); b4.w = cvt_tf32(b4.w);
                *(float4*)&Bs[nxt][krow[it] * GBPAD + 4 * nq[it]] = b4;
            }
        }
        __syncthreads();
    }

    // ---- epilogue ----
    #pragma unroll
    for (int mt = 0; mt < 4; mt++) {
        size_t row0 = (size_t)by * 128 + wr * 64 + 16 * mt + g;
        #pragma unroll
        for (int nt = 0; nt < 4; nt++) {
            int col = bx * 128 + wc * 32 + 8 * nt + 2 * t;
            float b0 = bias[col], b1 = bias[col + 1];
            *(float2*)&C[row0 * N + col] =
                make_float2(acc[mt][nt][0] + b0, acc[mt][nt][1] + b1);
            *(float2*)&C[(row0 + 8) * N + col] =
                make_float2(acc[mt][nt][2] + b0, acc[mt][nt][3] + b1);
        }
    }
}

// =====================================================================
// RoPE in-place on Q and K halves of g_qkv.
// =====================================================================
__global__ void rope_kernel(const float* __restrict__ cosE,
                            const float* __restrict__ sinE)
{
    int idx = blockIdx.x * blockDim.x + threadIdx.x;
    const int TOT = 2 * SEQ * NH * (HD / 2);
    if (idx >= TOT) return;
    int d    = idx % 40;
    int h    = (idx / 40) % NH;
    int s    = (idx / (40 * NH)) % SEQ;
    int part = idx / (40 * NH * SEQ);

    float* p = g_qkv + (size_t)s * QKVN + part * HIDDEN + h * HD;
    float t1 = p[d], t2 = p[d + 40];
    float c1 = cosE[s * HD + d],      s1 = sinE[s * HD + d];
    float c2 = cosE[s * HD + d + 40], s2 = sinE[s * HD + d + 40];
    p[d]      = t1 * c1 - t2 * s1;
    p[d + 40] = t2 * c2 + t1 * s2;
}

// =====================================================================
// TF32 flash attention, BM=64 x BN=64, 128 threads (4 warps),
// DOUBLE-BUFFERED K/V with register prefetch: one barrier per tile,
// LDG latency hidden behind mma. smem 103 KB -> 2 CTAs/SM.
// =====================================================================
#define FBM 64
#define FBN 64
#define QPAD 84
#define VPAD 88
#define SPAD 68
#define KBUF (FBN * QPAD)
#define VBUF (FBN * VPAD)
#define FA_SMEM_BYTES ((2*KBUF + 2*VBUF + FBM*SPAD) * 4)   // 105472

__global__ void __launch_bounds__(128, 2)
flash_attn_tc()
{
    extern __shared__ float sm[];
    float* Ks = sm;                    // [2][64][QPAD]
    float* Vs = Ks + 2 * KBUF;         // [2][64][VPAD]
    float* Sp = Vs + 2 * VBUF;         // [64][SPAD]

    int tid  = threadIdx.x;
    int lane = tid & 31;
    int w    = tid >> 5;
    int g    = lane >> 2;
    int t    = lane & 3;
    int h    = blockIdx.y;
    int q0   = blockIdx.x * FBM;

    // staging maps: 10 chunks of float4 per thread
    int sr[10], sc[10];
    #pragma unroll
    for (int j = 0; j < 10; j++) {
        int i = tid + 128 * j;
        sr[j] = i / 20;
        sc[j] = i % 20;
    }

    const float* qg  = g_qkv + (size_t)q0 * QKVN + h * HD;
    const float* kg0 = g_qkv + HIDDEN     + h * HD;
    const float* vg0 = g_qkv + 2 * HIDDEN + h * HD;

    // ---- prologue: Q -> Ks[1] (scratch), K0 -> Ks[0], V0 -> Vs[0] ----
    #pragma unroll
    for (int j = 0; j < 10; j++) {
        int r = sr[j], c = sc[j];
        float4 v = *(const float4*)&qg[(size_t)r * QKVN + 4 * c];
        v.x = cvt_tf32(v.x * INV_SCALE);
        v.y = cvt_tf32(v.y * INV_SCALE);
        v.z = cvt_tf32(v.z * INV_SCALE);
        v.w = cvt_tf32(v.w * INV_SCALE);
        *(float4*)&Ks[KBUF + r * QPAD + 4 * c] = v;

        float4 a = *(const float4*)&kg0[(size_t)r * QKVN + 4 * c];
        a.x = cvt_tf32(a.x); a.y = cvt_tf32(a.y);
        a.z = cvt_tf32(a.z); a.w = cvt_tf32(a.w);
        *(float4*)&Ks[r * QPAD + 4 * c] = a;

        float4 b = *(const float4*)&vg0[(size_t)r * QKVN + 4 * c];
        b.x = cvt_tf32(b.x); b.y = cvt_tf32(b.y);
        b.z = cvt_tf32(b.z); b.w = cvt_tf32(b.w);
        *(float4*)&Vs[r * VPAD + 4 * c] = b;
    }
    __syncthreads();

    // ---- Q fragments -> registers (from Ks[1]) ----
    uint32_t qf[10][4];
    {
        int r0 = KBUF + (16 * w + g) * QPAD;
        int r1 = KBUF + (16 * w + g + 8) * QPAD;
        #pragma unroll
        for (int s = 0; s < 10; s++) {
            qf[s][0] = __float_as_uint(Ks[r0 + 8 * s + t]);
            qf[s][1] = __float_as_uint(Ks[r1 + 8 * s + t]);
            qf[s][2] = __float_as_uint(Ks[r0 + 8 * s + t + 4]);
            qf[s][3] = __float_as_uint(Ks[r1 + 8 * s + t + 4]);
        }
    }
    __syncthreads();   // everyone has qf before Ks[1] is overwritten

    float o[10][4];
    #pragma unroll
    for (int n = 0; n < 10; n++)
        #pragma unroll
        for (int j = 0; j < 4; j++) o[n][j] = 0.f;
    float m0 = -3.0e38f, m1 = -3.0e38f, l0 = 0.f, l1 = 0.f;

    int pr0 = (16 * w + g) * SPAD;
    int pr1 = (16 * w + g + 8) * SPAD;

    #pragma unroll 1
    for (int kt = 0; kt < SEQ / FBN; kt++) {
        int cur = kt & 1, nxt = cur ^ 1;
        const float* Kc = Ks + cur * KBUF;
        const float* Vc = Vs + cur * VBUF;
        bool pf = (kt + 1 < SEQ / FBN);
        const float* kgn = kg0 + (size_t)(kt + 1) * FBN * QKVN;
        const float* vgn = vg0 + (size_t)(kt + 1) * FBN * QKVN;

        // prefetch next K into registers (hidden behind S-mma)
        float4 kr[10];
        if (pf) {
            #pragma unroll
            for (int j = 0; j < 10; j++)
                kr[j] = *(const float4*)&kgn[(size_t)sr[j] * QKVN + 4 * sc[j]];
        }

        // ---- S = Q K^T : 8 n-tiles x 10 k-steps ----
        float sacc[8][4];
        #pragma unroll
        for (int n = 0; n < 8; n++)
            #pragma unroll
            for (int j = 0; j < 4; j++) sacc[n][j] = 0.f;

        #pragma unroll
        for (int s = 0; s < 10; s++) {
            #pragma unroll
            for (int nt = 0; nt < 8; nt++) {
                uint32_t b0 = __float_as_uint(Kc[(8 * nt + g) * QPAD + 8 * s + t]);
                uint32_t b1 = __float_as_uint(Kc[(8 * nt + g) * QPAD + 8 * s + t + 4]);
                mma_tf32(sacc[nt], qf[s][0], qf[s][1], qf[s][2], qf[s][3], b0, b1);
            }
        }

        // store prefetched K into the other buffer
        if (pf) {
            #pragma unroll
            for (int j = 0; j < 10; j++) {
                float4 a = kr[j];
                a.x = cvt_tf32(a.x); a.y = cvt_tf32(a.y);
                a.z = cvt_tf32(a.z); a.w = cvt_tf32(a.w);
                *(float4*)&Ks[nxt * KBUF + sr[j] * QPAD + 4 * sc[j]] = a;
            }
        }

        // prefetch next V (hidden behind softmax + PV)
        float4 vr[10];
        if (pf) {
            #pragma unroll
            for (int j = 0; j < 10; j++)
                vr[j] = *(const float4*)&vgn[(size_t)sr[j] * QKVN + 4 * sc[j]];
        }

        // ---- online softmax ----
        float rmax0 = sacc[0][0], rmax1 = sacc[0][2];
        #pragma unroll
        for (int nt = 0; nt < 8; nt++) {
            rmax0 = fmaxf(rmax0, fmaxf(sacc[nt][0], sacc[nt][1]));
            rmax1 = fmaxf(rmax1, fmaxf(sacc[nt][2], sacc[nt][3]));
        }
        rmax0 = fmaxf(rmax0, __shfl_xor_sync(0xffffffffu, rmax0, 1));
        rmax0 = fmaxf(rmax0, __shfl_xor_sync(0xffffffffu, rmax0, 2));
        rmax1 = fmaxf(rmax1, __shfl_xor_sync(0xffffffffu, rmax1, 1));
        rmax1 = fmaxf(rmax1, __shfl_xor_sync(0xffffffffu, rmax1, 2));

        float mn0 = fmaxf(m0, rmax0), mn1 = fmaxf(m1, rmax1);
        float alpha0 = __expf(m0 - mn0), alpha1 = __expf(m1 - mn1);
        m0 = mn0; m1 = mn1;

        float rs0 = 0.f, rs1 = 0.f;
        #pragma unroll
        for (int nt = 0; nt < 8; nt++) {
            float p0 = __expf(sacc[nt][0] - mn0);
            float p1 = __expf(sacc[nt][1] - mn0);
            float p2 = __expf(sacc[nt][2] - mn1);
            float p3 = __expf(sacc[nt][3] - mn1);
            rs0 += p0 + p1;
            rs1 += p2 + p3;
            *(float2*)&Sp[pr0 + 8 * nt + 2 * t] = make_float2(cvt_tf32(p0), cvt_tf32(p1));
            *(float2*)&Sp[pr1 + 8 * nt + 2 * t] = make_float2(cvt_tf32(p2), cvt_tf32(p3));
        }
        rs0 += __shfl_xor_sync(0xffffffffu, rs0, 1);
        rs0 += __shfl_xor_sync(0xffffffffu, rs0, 2);
        rs1 += __shfl_xor_sync(0xffffffffu, rs1, 1);
        rs1 += __shfl_xor_sync(0xffffffffu, rs1, 2);
        l0 = l0 * alpha0 + rs0;
        l1 = l1 * alpha1 + rs1;

        #pragma unroll
        for (int n = 0; n < 10; n++) {
            o[n][0] *= alpha0; o[n][1] *= alpha0;
            o[n][2] *= alpha1; o[n][3] *= alpha1;
        }
        __syncwarp();   // P slab is warp-private

        // ---- O += P V : 8 k-steps x 10 n-tiles ----
        #pragma unroll
        for (int s = 0; s < 8; s++) {
            uint32_t a0 = __float_as_uint(Sp[pr0 + 8 * s + t]);
            uint32_t a1 = __float_as_uint(Sp[pr1 + 8 * s + t]);
            uint32_t a2 = __float_as_uint(Sp[pr0 + 8 * s + t + 4]);
            uint32_t a3 = __float_as_uint(Sp[pr1 + 8 * s + t + 4]);
            #pragma unroll
            for (int nt = 0; nt < 10; nt++) {
                uint32_t b0 = __float_as_uint(Vc[(8 * s + t    ) * VPAD + 8 * nt + g]);
                uint32_t b1 = __float_as_uint(Vc[(8 * s + t + 4) * VPAD + 8 * nt + g]);
                mma_tf32(o[nt], a0, a1, a2, a3, b0, b1);
            }
        }

        // store prefetched V into the other buffer
        if (pf) {
            #pragma unroll
            for (int j = 0; j < 10; j++) {
                float4 b = vr[j];
                b.x = cvt_tf32(b.x); b.y = cvt_tf32(b.y);
                b.z = cvt_tf32(b.z); b.w = cvt_tf32(b.w);
                *(float4*)&Vs[nxt * VBUF + sr[j] * VPAD + 4 * sc[j]] = b;
            }
        }
        __syncthreads();   // next-buffer writes complete; cur reads done
    }

    // ---- epilogue ----
    float il0 = 1.0f / l0, il1 = 1.0f / l1;
    size_t r0 = (size_t)(q0 + 16 * w + g);
    float* og0 = g_attn + r0 * HIDDEN + h * HD;
    float* og1 = og0 + 8 * HIDDEN;
    #pragma unroll
    for (int nt = 0; nt < 10; nt++) {
        *(float2*)&og0[8 * nt + 2 * t] = make_float2(o[nt][0] * il0, o[nt][1] * il0);
        *(float2*)&og1[8 * nt + 2 * t] = make_float2(o[nt][2] * il1, o[nt][3] * il1);
    }
}

// =====================================================================
extern "C" void kernel_launch(void* const* d_in, const int* in_sizes, int n_in,
                              void* d_out, int out_size)
{
    const float* x      = (const float*)d_in[0];
    const float* cosE   = (const float*)d_in[1];
    const float* sinE   = (const float*)d_in[2];
    const float* w_qkv  = (const float*)d_in[3];
    const float* b_qkv  = (const float*)d_in[4];
    const float* w_proj = (const float*)d_in[5];
    const float* b_proj = (const float*)d_in[6];
    float*       out    = (float*)d_out;

    float *qkv, *attn;
    cudaGetSymbolAddress((void**)&qkv,  g_qkv);
    cudaGetSymbolAddress((void**)&attn, g_attn);

    cudaFuncSetAttribute(flash_attn_tc,
                         cudaFuncAttributeMaxDynamicSharedMemorySize,
                         FA_SMEM_BYTES);

    // 1) QKV GEMM : [4096,1280] @ [1280,3840] + bias   (TF32, pipelined)
    sgemm_tf32<<<dim3(QKVN / 128, SEQ / 128), 256>>>(
        x, w_qkv, b_qkv, qkv, SEQ, QKVN, HIDDEN);

    // 2) RoPE on Q and K
    {
        int tot = 2 * SEQ * NH * (HD / 2);
        rope_kernel<<<(tot + 255) / 256, 256>>>(cosE, sinE);
    }

    // 3) TF32 flash attention (double-buffered, 2 CTAs/SM)
    flash_attn_tc<<<dim3(SEQ / FBM, NH), 128, FA_SMEM_BYTES>>>();

    // 4) output projection : [4096,1280] @ [1280,1280] + bias (TF32, pipelined)
    sgemm_tf32<<<dim3(HIDDEN / 128, SEQ / 128), 256>>>(
        attn, w_proj, b_proj, out, SEQ, HIDDEN, HIDDEN);
}

// round 10
// speedup vs baseline: 2.1124x; 1.1902x over previous
#include <cuda_runtime.h>
#include <math.h>
#include <stdint.h>

#define SEQ    4096
#define NH     16
#define HD     80
#define HIDDEN 1280
#define QKVN   3840
#define INV_SCALE 0.11180339887498948f   // 1/sqrt(80)
#define LOG2E     1.4426950408889634f

// -------- scratch (no allocation allowed -> __device__ globals) --------
__device__ __align__(16) float g_qkv [SEQ * QKVN];    // 62.9 MB
__device__ __align__(16) float g_attn[SEQ * HIDDEN];  // 21.0 MB
// head-packed, tf32-rounded tensors [NH][SEQ][HD]
__device__ __align__(16) float g_q[NH * SEQ * HD];    // 21.0 MB (pre-scaled)
__device__ __align__(16) float g_k[NH * SEQ * HD];    // 21.0 MB
__device__ __align__(16) float g_v[NH * SEQ * HD];    // 21.0 MB

// =====================================================================
// helpers
// =====================================================================
__device__ __forceinline__ float cvt_tf32(float x) {
    uint32_t u;
    asm("cvt.rna.tf32.f32 %0, %1;" : "=r"(u) : "f"(x));
    return __uint_as_float(u);
}
__device__ __forceinline__ float ex2(float x) {
    float y;
    asm("ex2.approx.ftz.f32 %0, %1;" : "=f"(y) : "f"(x));
    return y;
}
__device__ __forceinline__ void mma_tf32(float* c,
    uint32_t a0, uint32_t a1, uint32_t a2, uint32_t a3,
    uint32_t b0, uint32_t b1)
{
    asm volatile(
        "mma.sync.aligned.m16n8k8.row.col.f32.tf32.tf32.f32 "
        "{%0,%1,%2,%3}, {%4,%5,%6,%7}, {%8,%9}, {%0,%1,%2,%3};\n"
        : "+f"(c[0]), "+f"(c[1]), "+f"(c[2]), "+f"(c[3])
        : "r"(a0), "r"(a1), "r"(a2), "r"(a3), "r"(b0), "r"(b1));
}
__device__ __forceinline__ void cp16(uint32_t dst, const void* src) {
    asm volatile("cp.async.cg.shared.global [%0], [%1], 16;\n"
                 :: "r"(dst), "l"(src));
}
#define CP_COMMIT() asm volatile("cp.async.commit_group;\n" ::: "memory")
#define CP_WAIT1()  asm volatile("cp.async.wait_group 1;\n" ::: "memory")
#define CP_WAIT0()  asm volatile("cp.async.wait_group 0;\n" ::: "memory")

// =====================================================================
// TF32 tensor-core GEMM (unchanged from R9): 128x128x16, double-buffered.
// =====================================================================
#define GAPAD 20
#define GBPAD 136
#define GA_FLOATS (128 * GAPAD)
#define GB_FLOATS (16 * GBPAD)

__global__ void __launch_bounds__(256, 2)
sgemm_tf32(const float* __restrict__ A, const float* __restrict__ B,
           const float* __restrict__ bias, float* __restrict__ C,
           int M, int N, int K)
{
    __shared__ float As[2][GA_FLOATS];
    __shared__ float Bs[2][GB_FLOATS];

    int tid  = threadIdx.x;
    int lane = tid & 31;
    int w    = tid >> 5;
    int g    = lane >> 2;
    int t    = lane & 3;
    int wr   = w >> 2;
    int wc   = w & 3;
    int bx = blockIdx.x, by = blockIdx.y;

    const float* Ab = A + (size_t)by * 128 * K;
    const float* Bb = B + (size_t)bx * 128;

    int arow[2], acolq[2], krow[2], nq[2];
    #pragma unroll
    for (int it = 0; it < 2; it++) {
        int c = tid + it * 256;
        arow[it] = c >> 2;  acolq[it] = c & 3;
        krow[it] = c >> 5;  nq[it]    = c & 31;
    }

    float acc[4][4][4];
    #pragma unroll
    for (int mt = 0; mt < 4; mt++)
        #pragma unroll
        for (int nt = 0; nt < 4; nt++)
            #pragma unroll
            for (int j = 0; j < 4; j++) acc[mt][nt][j] = 0.f;

    const int NIT = K / 16;

    #pragma unroll
    for (int it = 0; it < 2; it++) {
        float4 a4 = *(const float4*)&Ab[(size_t)arow[it] * K + 4 * acolq[it]];
        a4.x = cvt_tf32(a4.x); a4.y = cvt_tf32(a4.y);
        a4.z = cvt_tf32(a4.z); a4.w = cvt_tf32(a4.w);
        *(float4*)&As[0][arow[it] * GAPAD + 4 * acolq[it]] = a4;
        float4 b4 = *(const float4*)&Bb[(size_t)krow[it] * N + 4 * nq[it]];
        b4.x = cvt_tf32(b4.x); b4.y = cvt_tf32(b4.y);
        b4.z = cvt_tf32(b4.z); b4.w = cvt_tf32(b4.w);
        *(float4*)&Bs[0][krow[it] * GBPAD + 4 * nq[it]] = b4;
    }
    __syncthreads();

    #pragma unroll 1
    for (int i = 0; i < NIT; i++) {
        int cur = i & 1, nxt = cur ^ 1;
        const float* Ac = As[cur];
        const float* Bc = Bs[cur];

        float4 pa[2], pb[2];
        bool pf = (i + 1 < NIT);
        if (pf) {
            int k0 = (i + 1) * 16;
            #pragma unroll
            for (int it = 0; it < 2; it++) {
                pa[it] = *(const float4*)&Ab[(size_t)arow[it] * K + k0 + 4 * acolq[it]];
                pb[it] = *(const float4*)&Bb[(size_t)(k0 + krow[it]) * N + 4 * nq[it]];
            }
        }

        #pragma unroll
        for (int s = 0; s < 2; s++) {
            uint32_t af[4][4], bf[4][2];
            #pragma unroll
            for (int mt = 0; mt < 4; mt++) {
                int mrow = wr * 64 + 16 * mt;
                af[mt][0] = __float_as_uint(Ac[(mrow + g    ) * GAPAD + 8 * s + t    ]);
                af[mt][1] = __float_as_uint(Ac[(mrow + g + 8) * GAPAD + 8 * s + t    ]);
                af[mt][2] = __float_as_uint(Ac[(mrow + g    ) * GAPAD + 8 * s + t + 4]);
                af[mt][3] = __float_as_uint(Ac[(mrow + g + 8) * GAPAD + 8 * s + t + 4]);
            }
            #pragma unroll
            for (int nt = 0; nt < 4; nt++) {
                int nb = wc * 32 + 8 * nt;
                bf[nt][0] = __float_as_uint(Bc[(8 * s + t    ) * GBPAD + nb + g]);
                bf[nt][1] = __float_as_uint(Bc[(8 * s + t + 4) * GBPAD + nb + g]);
            }
            #pragma unroll
            for (int mt = 0; mt < 4; mt++)
                #pragma unroll
                for (int nt = 0; nt < 4; nt++)
                    mma_tf32(acc[mt][nt], af[mt][0], af[mt][1], af[mt][2], af[mt][3],
                             bf[nt][0], bf[nt][1]);
        }

        if (pf) {
            #pragma unroll
            for (int it = 0; it < 2; it++) {
                float4 a4 = pa[it];
                a4.x = cvt_tf32(a4.x); a4.y = cvt_tf32(a4.y);
                a4.z = cvt_tf32(a4.z); a4.w = cvt_tf32(a4.w);
                *(float4*)&As[nxt][arow[it] * GAPAD + 4 * acolq[it]] = a4;
                float4 b4 = pb[it];
                b4.x = cvt_tf32(b4.x); b4.y = cvt_tf32(b4.y);
                b4.z = cvt_tf32(b4.z); b4.w = cvt_tf32(b4.w);
                *(float4*)&Bs[nxt][krow[it] * GBPAD + 4 * nq[it]] = b4;
            }
        }
        __syncthreads();
    }

    #pragma unroll
    for (int mt = 0; mt < 4; mt++) {
        size_t row0 = (size_t)by * 128 + wr * 64 + 16 * mt + g;
        #pragma unroll
        for (int nt = 0; nt < 4; nt++) {
            int col = bx * 128 + wc * 32 + 8 * nt + 2 * t;
            float b0 = bias[col], b1 = bias[col + 1];
            *(float2*)&C[row0 * N + col] =
                make_float2(acc[mt][nt][0] + b0, acc[mt][nt][1] + b1);
            *(float2*)&C[(row0 + 8) * N + col] =
                make_float2(acc[mt][nt][2] + b0, acc[mt][nt][3] + b1);
        }
    }
}

// =====================================================================
// RoPE + pack: rotate Q,K; scale Q by INV_SCALE*LOG2E; tf32-round Q,K,V;
// write head-packed [NH][SEQ][HD] buffers for the flash kernel.
// =====================================================================
__global__ void rope_pack(const float* __restrict__ cosE,
                          const float* __restrict__ sinE)
{
    int idx = blockIdx.x * blockDim.x + threadIdx.x;
    const int TOT = SEQ * NH * (HD / 2);
    if (idx >= TOT) return;
    int d = idx % 40;
    int h = (idx / 40) % NH;
    int s = idx / (40 * NH);

    const float* base = g_qkv + (size_t)s * QKVN + h * HD;
    float q1 = base[d],              q2 = base[d + 40];
    float k1 = base[HIDDEN + d],     k2 = base[HIDDEN + d + 40];
    float v1 = base[2*HIDDEN + d],   v2 = base[2*HIDDEN + d + 40];

    float c1 = cosE[s * HD + d],      s1 = sinE[s * HD + d];
    float c2 = cosE[s * HD + d + 40], s2 = sinE[s * HD + d + 40];

    const float SC2 = INV_SCALE * LOG2E;
    float qo1 = (q1 * c1 - q2 * s1) * SC2;
    float qo2 = (q2 * c2 + q1 * s2) * SC2;
    float ko1 = k1 * c1 - k2 * s1;
    float ko2 = k2 * c2 + k1 * s2;

    size_t o = ((size_t)h * SEQ + s) * HD + d;
    g_q[o]      = cvt_tf32(qo1);
    g_q[o + 40] = cvt_tf32(qo2);
    g_k[o]      = cvt_tf32(ko1);
    g_k[o + 40] = cvt_tf32(ko2);
    g_v[o]      = cvt_tf32(v1);
    g_v[o + 40] = cvt_tf32(v2);
}

// =====================================================================
// TF32 flash attention v4: BM=64 x BN=64, 128 threads (4 warps).
// K/V double-buffered via cp.async from pre-converted packed gmem.
// No in-loop cvt, no LDG->reg->STS round trip. 2 CTAs/SM.
// =====================================================================
#define FBM 64
#define FBN 64
#define QPAD 84
#define VPAD 88
#define SPAD 68
#define KBUF (FBN * QPAD)
#define VBUF (FBN * VPAD)
#define FA_SMEM_BYTES ((2*KBUF + 2*VBUF + FBM*SPAD) * 4)   // 105472

__global__ void __launch_bounds__(128, 2)
flash_attn_tc()
{
    extern __shared__ float sm[];
    float* Ks = sm;                    // [2][64][QPAD]  (buf0 first stages Q)
    float* Vs = Ks + 2 * KBUF;         // [2][64][VPAD]
    float* Sp = Vs + 2 * VBUF;         // [64][SPAD]

    uint32_t smb;
    asm("{ .reg .u64 t0; cvta.to.shared.u64 t0, %1; cvt.u32.u64 %0, t0; }"
        : "=r"(smb) : "l"(sm));
    const uint32_t KD0 = smb;                       // Ks buf0
    const uint32_t VD0 = smb + 2 * KBUF * 4;        // Vs buf0

    int tid  = threadIdx.x;
    int lane = tid & 31;
    int w    = tid >> 5;
    int g    = lane >> 2;
    int t    = lane & 3;
    int h    = blockIdx.y;
    int q0   = blockIdx.x * FBM;

    // staging map: 10 x 16B chunks per thread over a 64x80 tile
    int rr[10], cc[10];
    #pragma unroll
    for (int j = 0; j < 10; j++) {
        int ch = tid + 128 * j;        // 0..1279
        rr[j] = ch / 20;
        cc[j] = ch % 20;
    }

    const char* qg = (const char*)(g_q + ((size_t)h * SEQ + q0) * HD);
    const char* kg = (const char*)(g_k + (size_t)h * SEQ * HD);
    const char* vg = (const char*)(g_v + (size_t)h * SEQ * HD);

    // ---- prologue: Q -> Ks[0] ; K0 -> Ks[1] ; V0 -> Vs[0] ----
    #pragma unroll
    for (int j = 0; j < 10; j++)
        cp16(KD0 + rr[j] * 336 + cc[j] * 16, qg + rr[j] * 320 + cc[j] * 16);
    CP_COMMIT();
    #pragma unroll
    for (int j = 0; j < 10; j++) {
        cp16(KD0 + KBUF * 4 + rr[j] * 336 + cc[j] * 16, kg + rr[j] * 320 + cc[j] * 16);
        cp16(VD0 + rr[j] * 352 + cc[j] * 16,            vg + rr[j] * 320 + cc[j] * 16);
    }
    CP_COMMIT();
    CP_WAIT1();                        // Q group done
    __syncthreads();

    // ---- Q fragments -> registers (from Ks[0]) ----
    uint32_t qf[10][4];
    {
        int r0 = (16 * w + g) * QPAD;
        int r1 = (16 * w + g + 8) * QPAD;
        #pragma unroll
        for (int s = 0; s < 10; s++) {
            qf[s][0] = __float_as_uint(Ks[r0 + 8 * s + t]);
            qf[s][1] = __float_as_uint(Ks[r1 + 8 * s + t]);
            qf[s][2] = __float_as_uint(Ks[r0 + 8 * s + t + 4]);
            qf[s][3] = __float_as_uint(Ks[r1 + 8 * s + t + 4]);
        }
    }

    float o[10][4];
    #pragma unroll
    for (int n = 0; n < 10; n++)
        #pragma unroll
        for (int j = 0; j < 4; j++) o[n][j] = 0.f;
    float m0 = -3.0e38f, m1 = -3.0e38f, l0 = 0.f, l1 = 0.f;

    int pr0 = (16 * w + g) * SPAD;
    int pr1 = (16 * w + g + 8) * SPAD;

    const int NT = SEQ / FBN;
    #pragma unroll 1
    for (int kt = 0; kt < NT; kt++) {
        // barrier: everyone done reading the buffers tile kt+1 will overwrite
        // (at kt==0 this also protects the Q staging buffer until qf is read)
        __syncthreads();

        if (kt + 1 < NT) {
            // tile kt+1: K -> Ks[kt&1], V -> Vs[(kt+1)&1]
            const char* kn = kg + (size_t)(kt + 1) * FBN * HD * 4;
            const char* vn = vg + (size_t)(kt + 1) * FBN * HD * 4;
            uint32_t kd = KD0 + (uint32_t)(kt & 1) * KBUF * 4;
            uint32_t vd = VD0 + (uint32_t)((kt + 1) & 1) * VBUF * 4;
            #pragma unroll
            for (int j = 0; j < 10; j++) {
                cp16(kd + rr[j] * 336 + cc[j] * 16, kn + rr[j] * 320 + cc[j] * 16);
                cp16(vd + rr[j] * 352 + cc[j] * 16, vn + rr[j] * 320 + cc[j] * 16);
            }
            CP_COMMIT();
            CP_WAIT1();                // tile kt's group complete
        } else {
            CP_WAIT0();
        }
        __syncthreads();               // tile kt data visible to all

        const float* Kc = Ks + ((kt + 1) & 1) * KBUF;
        const float* Vc = Vs + (kt & 1) * VBUF;

        // ---- S = Q K^T : 8 n-tiles x 10 k-steps ----
        float sacc[8][4];
        #pragma unroll
        for (int n = 0; n < 8; n++)
            #pragma unroll
            for (int j = 0; j < 4; j++) sacc[n][j] = 0.f;

        #pragma unroll
        for (int s = 0; s < 10; s++) {
            #pragma unroll
            for (int nt = 0; nt < 8; nt++) {
                uint32_t b0 = __float_as_uint(Kc[(8 * nt + g) * QPAD + 8 * s + t]);
                uint32_t b1 = __float_as_uint(Kc[(8 * nt + g) * QPAD + 8 * s + t + 4]);
                mma_tf32(sacc[nt], qf[s][0], qf[s][1], qf[s][2], qf[s][3], b0, b1);
            }
        }

        // ---- online softmax (base-2 domain; log2e folded into Q) ----
        float rmax0 = sacc[0][0], rmax1 = sacc[0][2];
        #pragma unroll
        for (int nt = 0; nt < 8; nt++) {
            rmax0 = fmaxf(rmax0, fmaxf(sacc[nt][0], sacc[nt][1]));
            rmax1 = fmaxf(rmax1, fmaxf(sacc[nt][2], sacc[nt][3]));
        }
        rmax0 = fmaxf(rmax0, __shfl_xor_sync(0xffffffffu, rmax0, 1));
        rmax0 = fmaxf(rmax0, __shfl_xor_sync(0xffffffffu, rmax0, 2));
        rmax1 = fmaxf(rmax1, __shfl_xor_sync(0xffffffffu, rmax1, 1));
        rmax1 = fmaxf(rmax1, __shfl_xor_sync(0xffffffffu, rmax1, 2));

        float mn0 = fmaxf(m0, rmax0), mn1 = fmaxf(m1, rmax1);
        float alpha0 = ex2(m0 - mn0), alpha1 = ex2(m1 - mn1);
        m0 = mn0; m1 = mn1;

        float rs0 = 0.f, rs1 = 0.f;
        #pragma unroll
        for (int nt = 0; nt < 8; nt++) {
            float p0 = ex2(sacc[nt][0] - mn0);
            float p1 = ex2(sacc[nt][1] - mn0);
            float p2 = ex2(sacc[nt][2] - mn1);
            float p3 = ex2(sacc[nt][3] - mn1);
            rs0 += p0 + p1;
            rs1 += p2 + p3;
            *(float2*)&Sp[pr0 + 8 * nt + 2 * t] = make_float2(cvt_tf32(p0), cvt_tf32(p1));
            *(float2*)&Sp[pr1 + 8 * nt + 2 * t] = make_float2(cvt_tf32(p2), cvt_tf32(p3));
        }
        rs0 += __shfl_xor_sync(0xffffffffu, rs0, 1);
        rs0 += __shfl_xor_sync(0xffffffffu, rs0, 2);
        rs1 += __shfl_xor_sync(0xffffffffu, rs1, 1);
        rs1 += __shfl_xor_sync(0xffffffffu, rs1, 2);
        l0 = l0 * alpha0 + rs0;
        l1 = l1 * alpha1 + rs1;

        #pragma unroll
        for (int n = 0; n < 10; n++) {
            o[n][0] *= alpha0; o[n][1] *= alpha0;
            o[n][2] *= alpha1; o[n][3] *= alpha1;
        }
        __syncwarp();   // P slab is warp-private

        // ---- O += P V : 8 k-steps x 10 n-tiles ----
        #pragma unroll
        for (int s = 0; s < 8; s++) {
            uint32_t a0 = __float_as_uint(Sp[pr0 + 8 * s + t]);
            uint32_t a1 = __float_as_uint(Sp[pr1 + 8 * s + t]);
            uint32_t a2 = __float_as_uint(Sp[pr0 + 8 * s + t + 4]);
            uint32_t a3 = __float_as_uint(Sp[pr1 + 8 * s + t + 4]);
            #pragma unroll
            for (int nt = 0; nt < 10; nt++) {
                uint32_t b0 = __float_as_uint(Vc[(8 * s + t    ) * VPAD + 8 * nt + g]);
                uint32_t b1 = __float_as_uint(Vc[(8 * s + t + 4) * VPAD + 8 * nt + g]);
                mma_tf32(o[nt], a0, a1, a2, a3, b0, b1);
            }
        }
        __syncwarp();
    }

    // ---- epilogue ----
    float il0 = 1.0f / l0, il1 = 1.0f / l1;
    size_t r0 = (size_t)(q0 + 16 * w + g);
    float* og0 = g_attn + r0 * HIDDEN + h * HD;
    float* og1 = og0 + 8 * HIDDEN;
    #pragma unroll
    for (int nt = 0; nt < 10; nt++) {
        *(float2*)&og0[8 * nt + 2 * t] = make_float2(o[nt][0] * il0, o[nt][1] * il0);
        *(float2*)&og1[8 * nt + 2 * t] = make_float2(o[nt][2] * il1, o[nt][3] * il1);
    }
}

// =====================================================================
extern "C" void kernel_launch(void* const* d_in, const int* in_sizes, int n_in,
                              void* d_out, int out_size)
{
    const float* x      = (const float*)d_in[0];
    const float* cosE   = (const float*)d_in[1];
    const float* sinE   = (const float*)d_in[2];
    const float* w_qkv  = (const float*)d_in[3];
    const float* b_qkv  = (const float*)d_in[4];
    const float* w_proj = (const float*)d_in[5];
    const float* b_proj = (const float*)d_in[6];
    float*       out    = (float*)d_out;

    float *qkv, *attn;
    cudaGetSymbolAddress((void**)&qkv,  g_qkv);
    cudaGetSymbolAddress((void**)&attn, g_attn);

    cudaFuncSetAttribute(flash_attn_tc,
                         cudaFuncAttributeMaxDynamicSharedMemorySize,
                         FA_SMEM_BYTES);

    // 1) QKV GEMM : [4096,1280] @ [1280,3840] + bias   (TF32, pipelined)
    sgemm_tf32<<<dim3(QKVN / 128, SEQ / 128), 256>>>(
        x, w_qkv, b_qkv, qkv, SEQ, QKVN, HIDDEN);

    // 2) RoPE + tf32 pack into per-head buffers
    {
        int tot = SEQ * NH * (HD / 2);
        rope_pack<<<(tot + 255) / 256, 256>>>(cosE, sinE);
    }

    // 3) TF32 flash attention (cp.async double-buffered)
    flash_attn_tc<<<dim3(SEQ / FBM, NH), 128, FA_SMEM_BYTES>>>();

    // 4) output projection : [4096,1280] @ [1280,1280] + bias (TF32, pipelined)
    sgemm_tf32<<<dim3(HIDDEN / 128, SEQ / 128), 256>>>(
        attn, w_proj, b_proj, out, SEQ, HIDDEN, HIDDEN);
}